// round 6
// baseline (speedup 1.0000x reference)
#include <cuda_runtime.h>
#include <cstddef>
#include <cstdint>

typedef unsigned long long ull;

#define U2   (512*512)
#define NBLK 136
#define NTHR 256
#define ASTR 34                 // ull stride per A-dup row (pad: banks + 16B STS align)
#define BSTR 36                 // float stride per B row (pad: 16B cp.async align)
#define ASZ  (64*ASTR)          // ulls per A buffer
#define BSZ  (32*BSTR)          // floats per B buffer

// ---------------- device state (static, no allocation) ----------------
__device__ float g_H[2][3][U2];              // ping-pong hidden states
__device__ __align__(16) float g_W1[608*512];   // [WA0 ; WB0]
__device__ __align__(16) float g_W2[1024*512];  // [WA1 ; M01]
__device__ __align__(16) float g_W3[1024*512];  // [WA2 ; M12]
__device__ __align__(16) float g_W3e[1024*544]; // [W3 | W3@Mo]
__device__ __align__(16) float g_Mo[512*32];    // WC2 @ Wout
__device__ __align__(16) float g_acc[512*32];   // running accumulator mirror
__device__ __align__(16) float g_c0[512], g_c1[512], g_c2[512], g_co[32], g_co2[32];
__device__ unsigned g_bar_cnt, g_bar_gen;

// ---------------- small helpers ----------------
__device__ __forceinline__ void ffma2(ull& d, ull a, ull b) {
    asm("fma.rn.f32x2 %0, %1, %2, %0;" : "+l"(d) : "l"(a), "l"(b));
}
__device__ __forceinline__ float lof(ull a){ return __uint_as_float((unsigned)a); }
__device__ __forceinline__ float hif(ull a){ return __uint_as_float((unsigned)(a >> 32)); }

__device__ __forceinline__ void cp16(float* dst_smem, const float* src) {
    unsigned d = (unsigned)__cvta_generic_to_shared(dst_smem);
    asm volatile("cp.async.cg.shared.global [%0], [%1], 16;" :: "r"(d), "l"(src));
}
__device__ __forceinline__ void cp_commit() { asm volatile("cp.async.commit_group;"); }
template<int N> __device__ __forceinline__ void cp_wait() {
    asm volatile("cp.async.wait_group %0;" :: "n"(N));
}

// ---------------- grid barrier (136 co-resident CTAs) ----------------
__device__ __forceinline__ void grid_sync() {
    __syncthreads();
    if (threadIdx.x == 0) {
        __threadfence();
        volatile unsigned* vgen = &g_bar_gen;
        unsigned gen = *vgen;
        if (atomicAdd(&g_bar_cnt, 1u) == NBLK - 1u) {
            g_bar_cnt = 0;
            __threadfence();
            *vgen = gen + 1u;
        } else {
            while (*vgen == gen) { }
        }
        __threadfence();
    }
    __syncthreads();
}

// ---------------- A fill: gmem -> regs -> lane-duplicated smem ----------------
__device__ __forceinline__ void loadA(
    const float* __restrict__ A0, int s0, int e0,
    const float* __restrict__ A1, int s1, int e1,
    const float* __restrict__ A2, int s2,
    int row0, int kt, int rb, int f2, float2 v[4])
{
    const float* Ap; size_t st; int off;
    if (kt < e0)      { Ap = A0; st = (size_t)s0; off = 0; }
    else if (kt < e1) { Ap = A1; st = (size_t)s1; off = e0 * 32; }
    else              { Ap = A2; st = (size_t)s2; off = e1 * 32; }
    const int kloc = kt * 32 - off + 2 * f2;
    #pragma unroll
    for (int i = 0; i < 4; i++)
        v[i] = __ldcg((const float2*)(Ap + (size_t)(row0 + rb + 16*i) * st + kloc));
}

__device__ __forceinline__ void stsA(ull* As, int rb, int f2, const float2 v[4]) {
    #pragma unroll
    for (int i = 0; i < 4; i++) {
        unsigned addr = (unsigned)__cvta_generic_to_shared(As + (rb + 16*i) * ASTR + 2*f2);
        asm volatile("st.shared.v4.b32 [%0], {%1,%2,%3,%4};" :: "r"(addr),
            "r"(__float_as_uint(v[i].x)), "r"(__float_as_uint(v[i].x)),
            "r"(__float_as_uint(v[i].y)), "r"(__float_as_uint(v[i].y)));
    }
}

__device__ __forceinline__ void cpB(float* Bs, const float* __restrict__ Bm,
                                    int ncolB, int col0, int kt, int tid) {
    int kr = tid >> 3, c4 = (tid & 7) * 4;
    cp16(Bs + kr * BSTR + c4, Bm + (size_t)(kt * 32 + kr) * ncolB + col0 + c4);
}

// ---------------- inner product: 32 k, pure LDS.64 + FFMA2 ----------------
__device__ __forceinline__ void comp32(const ull* As, const float* Bs,
                                       int rg2, int cg4, ull acc[4]) {
    const ull* a0p = As + rg2 * ASTR;
    const ull* a1p = a0p + ASTR;
    const float* bp = Bs + cg4;
    #pragma unroll
    for (int k = 0; k < 32; k++) {
        ull b01 = *(const ull*)(bp + k * BSTR);
        ull b23 = *(const ull*)(bp + k * BSTR + 2);
        ull a0 = a0p[k];
        ull a1 = a1p[k];
        ffma2(acc[0], a0, b01); ffma2(acc[1], a0, b23);
        ffma2(acc[2], a1, b01); ffma2(acc[3], a1, b23);
    }
}

// ---------------- one GEMM stage (64x32 tile per CTA) ----------------
__device__ __forceinline__ void do_stage(
    const float* A0, int s0, int e0,
    const float* A1, int s1, int e1,
    const float* A2, int s2,
    const float* Bm, int ncolB, int nKt,
    int row0, int col0, ull* As, float* Bs, int tid, ull acc[4])
{
    const int rb = tid >> 4, f2 = tid & 15;
    const int rg2 = (tid >> 3) * 2, cg4 = (tid & 7) * 4;
    acc[0] = acc[1] = acc[2] = acc[3] = 0ull;

    float2 v[4];
    loadA(A0, s0, e0, A1, s1, e1, A2, s2, row0, 0, rb, f2, v);
    cpB(Bs, Bm, ncolB, col0, 0, tid);
    cp_commit();
    stsA(As, rb, f2, v);
    cp_wait<0>();
    __syncthreads();

    for (int kt = 0; kt < nKt; kt++) {
        const int cur = kt & 1, nxt = cur ^ 1;
        const bool more = (kt + 1 < nKt);
        if (more) {
            loadA(A0, s0, e0, A1, s1, e1, A2, s2, row0, kt + 1, rb, f2, v);
            cpB(Bs + nxt * BSZ, Bm, ncolB, col0, kt + 1, tid);
            cp_commit();
        }
        comp32(As + cur * ASZ, Bs + cur * BSZ, rg2, cg4, acc);
        if (more) {
            stsA(As + nxt * ASZ, rb, f2, v);
            cp_wait<0>();
        }
        __syncthreads();
    }
}

__device__ __forceinline__ void epi(float* C, const float* bias,
                                    int row0, int col0, int rg2, int cg4,
                                    const ull acc[4]) {
    float4 b = *(const float4*)(bias + col0 + cg4);
    float4 r0 = make_float4(lof(acc[0]) + b.x, hif(acc[0]) + b.y,
                            lof(acc[1]) + b.z, hif(acc[1]) + b.w);
    float4 r1 = make_float4(lof(acc[2]) + b.x, hif(acc[2]) + b.y,
                            lof(acc[3]) + b.z, hif(acc[3]) + b.w);
    __stcg((float4*)(C + (size_t)(row0 + rg2)     * 512 + col0 + cg4), r0);
    __stcg((float4*)(C + (size_t)(row0 + rg2 + 1) * 512 + col0 + cg4), r1);
}

// ---------------- persistent time-loop kernel ----------------
__global__ void __launch_bounds__(NTHR, 1) rnn_persistent(
    const float* __restrict__ x, float* __restrict__ out)
{
    __shared__ ull   As[2 * ASZ];
    __shared__ float Bs[2 * BSZ];
    const int tid = threadIdx.x;
    const int bid = blockIdx.x;

    {   // zero ping states + acc
        float* h0 = &g_H[0][0][0];
        const int n = 3 * U2;
        for (int i = bid * NTHR + tid; i < n + 512 * 32; i += NBLK * NTHR) {
            if (i < n) h0[i] = 0.f; else g_acc[i - n] = 0.f;
        }
    }
    grid_sync();

    const int rowt = bid / 17, colt = bid % 17;
    const int row0 = rowt * 64, col0 = colt * 32;
    const int rg2 = (tid >> 3) * 2, cg4 = (tid & 7) * 4;

    float4 accR0 = make_float4(0.f,0.f,0.f,0.f);
    float4 accR1 = make_float4(0.f,0.f,0.f,0.f);

    ull acc[4];
    for (int t = 0; t < 512; t++) {
        const float* Hin = &g_H[t & 1][0][0];
        float*       Hout = &g_H[(t & 1) ^ 1][0][0];

        // S1: H0' = [H0 | x_t | acc] @ W1 + c0    (19 k-tiles: 16+2+1)
        if (colt < 16) {
            do_stage(Hin, 512, 16, x + (size_t)t * 64, 32768, 18, g_acc, 32,
                     g_W1, 512, 19, row0, col0, As, Bs, tid, acc);
            epi(Hout, g_c0, row0, col0, rg2, cg4, acc);
        }
        grid_sync();

        // S2: H1' = [H1 | H0'] @ W2 + c1
        if (colt < 16) {
            do_stage(Hin + U2, 512, 16, Hout, 512, 32, Hout, 512,
                     g_W2, 512, 32, row0, col0, As, Bs, tid, acc);
            epi(Hout + U2, g_c1, row0, col0, rg2, cg4, acc);
        }
        grid_sync();

        // S3: [H2' | res] = [H2 | H1'] @ W3e + [c2 | co2]
        do_stage(Hin + 2*U2, 512, 16, Hout + U2, 512, 32, Hout, 512,
                 g_W3e, 544, 32, row0, col0, As, Bs, tid, acc);
        if (colt < 16) {
            epi(Hout + 2*U2, g_c2, row0, col0, rg2, cg4, acc);
        } else {
            float4 b = *(const float4*)(g_co2 + cg4);
            float4 r0 = make_float4(lof(acc[0]) + b.x, hif(acc[0]) + b.y,
                                    lof(acc[1]) + b.z, hif(acc[1]) + b.w);
            float4 r1 = make_float4(lof(acc[2]) + b.x, hif(acc[2]) + b.y,
                                    lof(acc[3]) + b.z, hif(acc[3]) + b.w);
            accR0.x += r0.x; accR0.y += r0.y; accR0.z += r0.z; accR0.w += r0.w;
            accR1.x += r1.x; accR1.y += r1.y; accR1.z += r1.z; accR1.w += r1.w;
            const int b0 = row0 + rg2;
            *(float4*)(out + (size_t)b0 * 16384 + (size_t)t * 32 + cg4) = r0;
            *(float4*)(out + (size_t)(b0 + 1) * 16384 + (size_t)t * 32 + cg4) = r1;
            __stcg((float4*)(g_acc + b0 * 32 + cg4), accR0);
            __stcg((float4*)(g_acc + (b0 + 1) * 32 + cg4), accR1);
        }
        grid_sync();
    }
}

// ---------------- prologue fold kernels (run once per launch) ----------------
__global__ void __launch_bounds__(256) stage_gemm(
    const float* __restrict__ A0, int s0, int e0,
    const float* __restrict__ A1, int s1, int e1,
    const float* __restrict__ A2, int s2,
    const float* __restrict__ Bm, const float* __restrict__ bias,
    float* __restrict__ C, int nKt)
{
    __shared__ float Asl[64][33];
    __shared__ float Bsl[32][33];
    const int tid  = threadIdx.x;
    const int row0 = (blockIdx.x >> 4) * 64;
    const int col0 = (blockIdx.x & 15) * 32;
    const int rg   = tid >> 4;
    const int cg   = tid & 15;
    float acc[4][2] = {};
    for (int kt = 0; kt < nKt; kt++) {
        const float* Ap; int st; int off;
        if (kt < e0)      { Ap = A0; st = s0; off = 0; }
        else if (kt < e1) { Ap = A1; st = s1; off = e0 * 32; }
        else              { Ap = A2; st = s2; off = e1 * 32; }
        const int kloc = kt * 32 - off;
        #pragma unroll
        for (int i = 0; i < 2; i++) {
            int e = tid + 256 * i; int r = e >> 3; int k4 = (e & 7) * 4;
            float4 v = *(const float4*)(Ap + (size_t)(row0 + r) * st + kloc + k4);
            Asl[r][k4+0]=v.x; Asl[r][k4+1]=v.y; Asl[r][k4+2]=v.z; Asl[r][k4+3]=v.w;
        }
        {
            int kr = tid >> 3; int c4 = (tid & 7) * 4;
            float4 v = *(const float4*)(Bm + (size_t)(kt*32 + kr) * 512 + col0 + c4);
            Bsl[kr][c4+0]=v.x; Bsl[kr][c4+1]=v.y; Bsl[kr][c4+2]=v.z; Bsl[kr][c4+3]=v.w;
        }
        __syncthreads();
        #pragma unroll
        for (int k = 0; k < 32; k++) {
            float b0 = Bsl[k][cg*2], b1 = Bsl[k][cg*2+1];
            #pragma unroll
            for (int r = 0; r < 4; r++) {
                float a = Asl[rg*4 + r][k];
                acc[r][0] += a * b0; acc[r][1] += a * b1;
            }
        }
        __syncthreads();
    }
    #pragma unroll
    for (int r = 0; r < 4; r++) {
        int row = row0 + rg*4 + r;
        #pragma unroll
        for (int j = 0; j < 2; j++) {
            int col = col0 + cg*2 + j;
            float b = bias ? bias[col] : 0.f;
            C[(size_t)row * 512 + col] = acc[r][j] + b;
        }
    }
}

__global__ void fold_mo(const float* __restrict__ WC2, const float* __restrict__ Wout) {
    int g = blockIdx.x * blockDim.x + threadIdx.x;  // 16384
    int k = g >> 5, p = g & 31;
    float s = 0.f;
    #pragma unroll 4
    for (int j = 0; j < 512; j++) s += WC2[(size_t)k*512 + j] * Wout[j*32 + p];
    g_Mo[k*32 + p] = s;
}

__global__ void build_w3e() {
    int g = blockIdx.x * blockDim.x + threadIdx.x;  // 1024*544
    if (g >= 1024 * 544) return;
    int r = g / 544, c = g % 544;
    if (c < 512) {
        g_W3e[g] = g_W3[(size_t)r * 512 + c];
    } else {
        float s = 0.f;
        #pragma unroll 4
        for (int k = 0; k < 512; k++)
            s += g_W3[(size_t)r * 512 + k] * g_Mo[k * 32 + (c - 512)];
        g_W3e[g] = s;
    }
}

__global__ void bias_kernel(const float* __restrict__ bA,  const float* __restrict__ bB0,
                            const float* __restrict__ bBr, const float* __restrict__ bC,
                            const float* __restrict__ Wout,const float* __restrict__ bout,
                            const float* __restrict__ WBr) {
    int n = threadIdx.x;  // 512 threads
    g_c0[n] = bA[n] + bB0[n];
    float s1 = 0.f, s2 = 0.f;
    for (int k = 0; k < 512; k++) {
        s1 += bC[k]       * WBr[(size_t)k*512 + n];
        s2 += bC[512 + k] * WBr[(size_t)U2 + (size_t)k*512 + n];
    }
    g_c1[n] = bA[512 + n]  + bBr[n]       + s1;
    g_c2[n] = bA[1024 + n] + bBr[512 + n] + s2;
    if (n < 32) {
        float s = 0.f;
        for (int k = 0; k < 512; k++) s += bC[1024 + k] * Wout[k*32 + n];
        g_co[n] = bout[n] + s;
    }
}

__global__ void co2_kernel() {
    int p = threadIdx.x;  // 32 threads; needs g_c2, g_Mo, g_co
    float s = 0.f;
    for (int k = 0; k < 512; k++) s += g_c2[k] * g_Mo[k * 32 + p];
    g_co2[p] = g_co[p] + s;
}

// ---------------- host launch ----------------
extern "C" void kernel_launch(void* const* d_in, const int* in_sizes, int n_in,
                              void* d_out, int out_size)
{
    const float* x    = (const float*)d_in[0];
    const float* WA   = (const float*)d_in[1];
    const float* bA   = (const float*)d_in[2];
    const float* WB0  = (const float*)d_in[3];
    const float* bB0  = (const float*)d_in[4];
    const float* WBr  = (const float*)d_in[5];
    const float* bBr  = (const float*)d_in[6];
    const float* WC   = (const float*)d_in[7];
    const float* bC   = (const float*)d_in[8];
    const float* Wout = (const float*)d_in[9];
    const float* bout = (const float*)d_in[10];
    float* out = (float*)d_out;

    float *W1, *W2, *W3;
    cudaGetSymbolAddress((void**)&W1, g_W1);
    cudaGetSymbolAddress((void**)&W2, g_W2);
    cudaGetSymbolAddress((void**)&W3, g_W3);

    cudaMemcpyAsync(W1,      WA,          (size_t)U2 * 4,       cudaMemcpyDeviceToDevice);
    cudaMemcpyAsync(W1 + U2, WB0,         (size_t)96 * 512 * 4, cudaMemcpyDeviceToDevice);
    cudaMemcpyAsync(W2,      WA + U2,     (size_t)U2 * 4,       cudaMemcpyDeviceToDevice);
    cudaMemcpyAsync(W3,      WA + 2 * U2, (size_t)U2 * 4,       cudaMemcpyDeviceToDevice);
    // M01 = WC0 @ WBr0 ; M12 = WC1 @ WBr1
    stage_gemm<<<128, 256>>>(WC,      512, 16, WC, 512, 16, WC, 512,
                             WBr,      nullptr, W2 + U2, 16);
    stage_gemm<<<128, 256>>>(WC + U2, 512, 16, WC, 512, 16, WC, 512,
                             WBr + U2, nullptr, W3 + U2, 16);
    fold_mo<<<64, 256>>>(WC + 2 * U2, Wout);
    bias_kernel<<<1, 512>>>(bA, bB0, bBr, bC, Wout, bout, WBr);
    co2_kernel<<<1, 32>>>();
    build_w3e<<<(1024 * 544 + 255) / 256, 256>>>();

    rnn_persistent<<<NBLK, NTHR>>>(x, out);
}

// round 7
// speedup vs baseline: 1.0030x; 1.0030x over previous
#include <cuda_runtime.h>
#include <cstddef>
#include <cstdint>

typedef unsigned long long ull;

#define U2   (512*512)
#define NBLK 136
#define NTHR 256
#define ASTR 34                 // ull stride per A-dup row (pad: banks + 16B STS align)
#define BSTR 36                 // float stride per B row (pad: 16B cp.async align)
#define ASZ  (64*ASTR)          // ulls per A buffer
#define BSZ  (32*BSTR)          // floats per B buffer

// ---------------- device state (static, no allocation) ----------------
__device__ float g_H[2][3][U2];              // ping-pong hidden states
__device__ __align__(16) float g_W1[608*512];   // [WA0 ; WB0]
__device__ __align__(16) float g_W2[1024*512];  // [WA1 ; M01]
__device__ __align__(16) float g_W3[1024*512];  // [WA2 ; M12]
__device__ __align__(16) float g_W3e[1024*544]; // [W3 | W3@Mo]
__device__ __align__(16) float g_Mo[512*32];    // WC2 @ Wout
__device__ __align__(16) float g_acc[512*32];   // running accumulator mirror
__device__ __align__(16) float g_c0[512], g_c1[512], g_c2[512], g_co[32], g_co2[32];
__device__ unsigned g_bar_cnt, g_bar_gen;

// ---------------- small helpers ----------------
__device__ __forceinline__ void ffma2(ull& d, ull a, ull b) {
    asm("fma.rn.f32x2 %0, %1, %2, %0;" : "+l"(d) : "l"(a), "l"(b));
}
__device__ __forceinline__ float lof(ull a){ return __uint_as_float((unsigned)a); }
__device__ __forceinline__ float hif(ull a){ return __uint_as_float((unsigned)(a >> 32)); }

__device__ __forceinline__ void cp16(float* dst_smem, const float* src) {
    unsigned d = (unsigned)__cvta_generic_to_shared(dst_smem);
    asm volatile("cp.async.cg.shared.global [%0], [%1], 16;" :: "r"(d), "l"(src));
}
__device__ __forceinline__ void cp_commit() { asm volatile("cp.async.commit_group;"); }
template<int N> __device__ __forceinline__ void cp_wait() {
    asm volatile("cp.async.wait_group %0;" :: "n"(N));
}

// ---------------- grid barrier (136 co-resident CTAs) ----------------
__device__ __forceinline__ void grid_sync() {
    __syncthreads();
    if (threadIdx.x == 0) {
        __threadfence();
        volatile unsigned* vgen = &g_bar_gen;
        unsigned gen = *vgen;
        if (atomicAdd(&g_bar_cnt, 1u) == NBLK - 1u) {
            g_bar_cnt = 0;
            __threadfence();
            *vgen = gen + 1u;
        } else {
            while (*vgen == gen) { }
        }
        __threadfence();
    }
    __syncthreads();
}

// ---------------- A fill: gmem -> regs -> lane-duplicated smem ----------------
__device__ __forceinline__ void loadA(
    const float* __restrict__ A0, int s0, int e0,
    const float* __restrict__ A1, int s1, int e1,
    const float* __restrict__ A2, int s2,
    int row0, int kt, int rb, int f2, float2 v[4])
{
    const float* Ap; size_t st; int off;
    if (kt < e0)      { Ap = A0; st = (size_t)s0; off = 0; }
    else if (kt < e1) { Ap = A1; st = (size_t)s1; off = e0 * 32; }
    else              { Ap = A2; st = (size_t)s2; off = e1 * 32; }
    const int kloc = kt * 32 - off + 2 * f2;
    #pragma unroll
    for (int i = 0; i < 4; i++)
        v[i] = __ldcg((const float2*)(Ap + (size_t)(row0 + rb + 16*i) * st + kloc));
}

__device__ __forceinline__ void stsA(ull* As, int rb, int f2, const float2 v[4]) {
    #pragma unroll
    for (int i = 0; i < 4; i++) {
        unsigned addr = (unsigned)__cvta_generic_to_shared(As + (rb + 16*i) * ASTR + 2*f2);
        asm volatile("st.shared.v4.b32 [%0], {%1,%2,%3,%4};" :: "r"(addr),
            "r"(__float_as_uint(v[i].x)), "r"(__float_as_uint(v[i].x)),
            "r"(__float_as_uint(v[i].y)), "r"(__float_as_uint(v[i].y)));
    }
}

__device__ __forceinline__ void cpB(float* Bs, const float* __restrict__ Bm,
                                    int ncolB, int col0, int kt, int tid) {
    int kr = tid >> 3, c4 = (tid & 7) * 4;
    cp16(Bs + kr * BSTR + c4, Bm + (size_t)(kt * 32 + kr) * ncolB + col0 + c4);
}

// ---------------- inner product: 32 k, pure LDS.64 + FFMA2 ----------------
__device__ __forceinline__ void comp32(const ull* As, const float* Bs,
                                       int rg2, int cg4, ull acc[4]) {
    const ull* a0p = As + rg2 * ASTR;
    const ull* a1p = a0p + ASTR;
    const float* bp = Bs + cg4;
    #pragma unroll
    for (int k = 0; k < 32; k++) {
        ull b01 = *(const ull*)(bp + k * BSTR);
        ull b23 = *(const ull*)(bp + k * BSTR + 2);
        ull a0 = a0p[k];
        ull a1 = a1p[k];
        ffma2(acc[0], a0, b01); ffma2(acc[1], a0, b23);
        ffma2(acc[2], a1, b01); ffma2(acc[3], a1, b23);
    }
}

// ---------------- one GEMM stage (64x32 tile per CTA) ----------------
__device__ __forceinline__ void do_stage(
    const float* A0, int s0, int e0,
    const float* A1, int s1, int e1,
    const float* A2, int s2,
    const float* Bm, int ncolB, int nKt,
    int row0, int col0, ull* As, float* Bs, int tid, ull acc[4])
{
    const int rb = tid >> 4, f2 = tid & 15;
    const int rg2 = (tid >> 3) * 2, cg4 = (tid & 7) * 4;
    acc[0] = acc[1] = acc[2] = acc[3] = 0ull;

    float2 v[4];
    loadA(A0, s0, e0, A1, s1, e1, A2, s2, row0, 0, rb, f2, v);
    cpB(Bs, Bm, ncolB, col0, 0, tid);
    cp_commit();
    stsA(As, rb, f2, v);
    cp_wait<0>();
    __syncthreads();

    for (int kt = 0; kt < nKt; kt++) {
        const int cur = kt & 1, nxt = cur ^ 1;
        const bool more = (kt + 1 < nKt);
        if (more) {
            loadA(A0, s0, e0, A1, s1, e1, A2, s2, row0, kt + 1, rb, f2, v);
            cpB(Bs + nxt * BSZ, Bm, ncolB, col0, kt + 1, tid);
            cp_commit();
        }
        comp32(As + cur * ASZ, Bs + cur * BSZ, rg2, cg4, acc);
        if (more) {
            stsA(As + nxt * ASZ, rb, f2, v);
            cp_wait<0>();
        }
        __syncthreads();
    }
}

__device__ __forceinline__ void epi(float* C, const float* bias,
                                    int row0, int col0, int rg2, int cg4,
                                    const ull acc[4]) {
    float4 b = *(const float4*)(bias + col0 + cg4);
    float4 r0 = make_float4(lof(acc[0]) + b.x, hif(acc[0]) + b.y,
                            lof(acc[1]) + b.z, hif(acc[1]) + b.w);
    float4 r1 = make_float4(lof(acc[2]) + b.x, hif(acc[2]) + b.y,
                            lof(acc[3]) + b.z, hif(acc[3]) + b.w);
    __stcg((float4*)(C + (size_t)(row0 + rg2)     * 512 + col0 + cg4), r0);
    __stcg((float4*)(C + (size_t)(row0 + rg2 + 1) * 512 + col0 + cg4), r1);
}

// ---------------- persistent time-loop kernel ----------------
__global__ void __launch_bounds__(NTHR, 1) rnn_persistent(
    const float* __restrict__ x, float* __restrict__ out)
{
    __shared__ ull   As[2 * ASZ];
    __shared__ float Bs[2 * BSZ];
    const int tid = threadIdx.x;
    const int bid = blockIdx.x;

    {   // zero ping states + acc
        float* h0 = &g_H[0][0][0];
        const int n = 3 * U2;
        for (int i = bid * NTHR + tid; i < n + 512 * 32; i += NBLK * NTHR) {
            if (i < n) h0[i] = 0.f; else g_acc[i - n] = 0.f;
        }
    }
    grid_sync();

    const int rowt = bid / 17, colt = bid % 17;
    const int row0 = rowt * 64, col0 = colt * 32;
    const int rg2 = (tid >> 3) * 2, cg4 = (tid & 7) * 4;

    float4 accR0 = make_float4(0.f,0.f,0.f,0.f);
    float4 accR1 = make_float4(0.f,0.f,0.f,0.f);

    ull acc[4];
    for (int t = 0; t < 512; t++) {
        const float* Hin = &g_H[t & 1][0][0];
        float*       Hout = &g_H[(t & 1) ^ 1][0][0];

        // S1: H0' = [H0 | x_t | acc] @ W1 + c0    (19 k-tiles: 16+2+1)
        if (colt < 16) {
            do_stage(Hin, 512, 16, x + (size_t)t * 64, 32768, 18, g_acc, 32,
                     g_W1, 512, 19, row0, col0, As, Bs, tid, acc);
            epi(Hout, g_c0, row0, col0, rg2, cg4, acc);
        }
        grid_sync();

        // S2: H1' = [H1 | H0'] @ W2 + c1
        if (colt < 16) {
            do_stage(Hin + U2, 512, 16, Hout, 512, 32, Hout, 512,
                     g_W2, 512, 32, row0, col0, As, Bs, tid, acc);
            epi(Hout + U2, g_c1, row0, col0, rg2, cg4, acc);
        }
        grid_sync();

        // S3: [H2' | res] = [H2 | H1'] @ W3e + [c2 | co2]
        do_stage(Hin + 2*U2, 512, 16, Hout + U2, 512, 32, Hout, 512,
                 g_W3e, 544, 32, row0, col0, As, Bs, tid, acc);
        if (colt < 16) {
            epi(Hout + 2*U2, g_c2, row0, col0, rg2, cg4, acc);
        } else {
            float4 b = *(const float4*)(g_co2 + cg4);
            float4 r0 = make_float4(lof(acc[0]) + b.x, hif(acc[0]) + b.y,
                                    lof(acc[1]) + b.z, hif(acc[1]) + b.w);
            float4 r1 = make_float4(lof(acc[2]) + b.x, hif(acc[2]) + b.y,
                                    lof(acc[3]) + b.z, hif(acc[3]) + b.w);
            accR0.x += r0.x; accR0.y += r0.y; accR0.z += r0.z; accR0.w += r0.w;
            accR1.x += r1.x; accR1.y += r1.y; accR1.z += r1.z; accR1.w += r1.w;
            const int b0 = row0 + rg2;
            *(float4*)(out + (size_t)b0 * 16384 + (size_t)t * 32 + cg4) = r0;
            *(float4*)(out + (size_t)(b0 + 1) * 16384 + (size_t)t * 32 + cg4) = r1;
            __stcg((float4*)(g_acc + b0 * 32 + cg4), accR0);
            __stcg((float4*)(g_acc + (b0 + 1) * 32 + cg4), accR1);
        }
        grid_sync();
    }
}

// ---------------- prologue fold kernels (run once per launch) ----------------
__global__ void __launch_bounds__(256) stage_gemm(
    const float* __restrict__ A0, int s0, int e0,
    const float* __restrict__ A1, int s1, int e1,
    const float* __restrict__ A2, int s2,
    const float* __restrict__ Bm, const float* __restrict__ bias,
    float* __restrict__ C, int nKt)
{
    __shared__ float Asl[64][33];
    __shared__ float Bsl[32][33];
    const int tid  = threadIdx.x;
    const int row0 = (blockIdx.x >> 4) * 64;
    const int col0 = (blockIdx.x & 15) * 32;
    const int rg   = tid >> 4;
    const int cg   = tid & 15;
    float acc[4][2] = {};
    for (int kt = 0; kt < nKt; kt++) {
        const float* Ap; int st; int off;
        if (kt < e0)      { Ap = A0; st = s0; off = 0; }
        else if (kt < e1) { Ap = A1; st = s1; off = e0 * 32; }
        else              { Ap = A2; st = s2; off = e1 * 32; }
        const int kloc = kt * 32 - off;
        #pragma unroll
        for (int i = 0; i < 2; i++) {
            int e = tid + 256 * i; int r = e >> 3; int k4 = (e & 7) * 4;
            float4 v = *(const float4*)(Ap + (size_t)(row0 + r) * st + kloc + k4);
            Asl[r][k4+0]=v.x; Asl[r][k4+1]=v.y; Asl[r][k4+2]=v.z; Asl[r][k4+3]=v.w;
        }
        {
            int kr = tid >> 3; int c4 = (tid & 7) * 4;
            float4 v = *(const float4*)(Bm + (size_t)(kt*32 + kr) * 512 + col0 + c4);
            Bsl[kr][c4+0]=v.x; Bsl[kr][c4+1]=v.y; Bsl[kr][c4+2]=v.z; Bsl[kr][c4+3]=v.w;
        }
        __syncthreads();
        #pragma unroll
        for (int k = 0; k < 32; k++) {
            float b0 = Bsl[k][cg*2], b1 = Bsl[k][cg*2+1];
            #pragma unroll
            for (int r = 0; r < 4; r++) {
                float a = Asl[rg*4 + r][k];
                acc[r][0] += a * b0; acc[r][1] += a * b1;
            }
        }
        __syncthreads();
    }
    #pragma unroll
    for (int r = 0; r < 4; r++) {
        int row = row0 + rg*4 + r;
        #pragma unroll
        for (int j = 0; j < 2; j++) {
            int col = col0 + cg*2 + j;
            float b = bias ? bias[col] : 0.f;
            C[(size_t)row * 512 + col] = acc[r][j] + b;
        }
    }
}

__global__ void fold_mo(const float* __restrict__ WC2, const float* __restrict__ Wout) {
    int g = blockIdx.x * blockDim.x + threadIdx.x;  // 16384
    int k = g >> 5, p = g & 31;
    float s = 0.f;
    #pragma unroll 4
    for (int j = 0; j < 512; j++) s += WC2[(size_t)k*512 + j] * Wout[j*32 + p];
    g_Mo[k*32 + p] = s;
}

__global__ void build_w3e() {
    int g = blockIdx.x * blockDim.x + threadIdx.x;  // 1024*544
    if (g >= 1024 * 544) return;
    int r = g / 544, c = g % 544;
    if (c < 512) {
        g_W3e[g] = g_W3[(size_t)r * 512 + c];
    } else {
        float s = 0.f;
        #pragma unroll 4
        for (int k = 0; k < 512; k++)
            s += g_W3[(size_t)r * 512 + k] * g_Mo[k * 32 + (c - 512)];
        g_W3e[g] = s;
    }
}

__global__ void bias_kernel(const float* __restrict__ bA,  const float* __restrict__ bB0,
                            const float* __restrict__ bBr, const float* __restrict__ bC,
                            const float* __restrict__ Wout,const float* __restrict__ bout,
                            const float* __restrict__ WBr) {
    int n = threadIdx.x;  // 512 threads
    g_c0[n] = bA[n] + bB0[n];
    float s1 = 0.f, s2 = 0.f;
    for (int k = 0; k < 512; k++) {
        s1 += bC[k]       * WBr[(size_t)k*512 + n];
        s2 += bC[512 + k] * WBr[(size_t)U2 + (size_t)k*512 + n];
    }
    g_c1[n] = bA[512 + n]  + bBr[n]       + s1;
    g_c2[n] = bA[1024 + n] + bBr[512 + n] + s2;
    if (n < 32) {
        float s = 0.f;
        for (int k = 0; k < 512; k++) s += bC[1024 + k] * Wout[k*32 + n];
        g_co[n] = bout[n] + s;
    }
}

__global__ void co2_kernel() {
    int p = threadIdx.x;  // 32 threads; needs g_c2, g_Mo, g_co
    float s = 0.f;
    for (int k = 0; k < 512; k++) s += g_c2[k] * g_Mo[k * 32 + p];
    g_co2[p] = g_co[p] + s;
}

// ---------------- host launch ----------------
extern "C" void kernel_launch(void* const* d_in, const int* in_sizes, int n_in,
                              void* d_out, int out_size)
{
    const float* x    = (const float*)d_in[0];
    const float* WA   = (const float*)d_in[1];
    const float* bA   = (const float*)d_in[2];
    const float* WB0  = (const float*)d_in[3];
    const float* bB0  = (const float*)d_in[4];
    const float* WBr  = (const float*)d_in[5];
    const float* bBr  = (const float*)d_in[6];
    const float* WC   = (const float*)d_in[7];
    const float* bC   = (const float*)d_in[8];
    const float* Wout = (const float*)d_in[9];
    const float* bout = (const float*)d_in[10];
    float* out = (float*)d_out;

    float *W1, *W2, *W3;
    cudaGetSymbolAddress((void**)&W1, g_W1);
    cudaGetSymbolAddress((void**)&W2, g_W2);
    cudaGetSymbolAddress((void**)&W3, g_W3);

    cudaMemcpyAsync(W1,      WA,          (size_t)U2 * 4,       cudaMemcpyDeviceToDevice);
    cudaMemcpyAsync(W1 + U2, WB0,         (size_t)96 * 512 * 4, cudaMemcpyDeviceToDevice);
    cudaMemcpyAsync(W2,      WA + U2,     (size_t)U2 * 4,       cudaMemcpyDeviceToDevice);
    cudaMemcpyAsync(W3,      WA + 2 * U2, (size_t)U2 * 4,       cudaMemcpyDeviceToDevice);
    // M01 = WC0 @ WBr0 ; M12 = WC1 @ WBr1
    stage_gemm<<<128, 256>>>(WC,      512, 16, WC, 512, 16, WC, 512,
                             WBr,      nullptr, W2 + U2, 16);
    stage_gemm<<<128, 256>>>(WC + U2, 512, 16, WC, 512, 16, WC, 512,
                             WBr + U2, nullptr, W3 + U2, 16);
    fold_mo<<<64, 256>>>(WC + 2 * U2, Wout);
    bias_kernel<<<1, 512>>>(bA, bB0, bBr, bC, Wout, bout, WBr);
    co2_kernel<<<1, 32>>>();
    build_w3e<<<(1024 * 544 + 255) / 256, 256>>>();

    rnn_persistent<<<NBLK, NTHR>>>(x, out);
}